// round 9
// baseline (speedup 1.0000x reference)
#include <cuda_runtime.h>
#include <cuda_pipeline.h>
#include <math.h>

#define N_TOK  16384
#define DIM    4096
#define NEXP   64
#define TOPK   8
#define TPB    128               // tokens per tile
#define NTHR   256               // 8 warps
#define KC     64                // k per chunk
#define KSTEPS (KC / 16)         // 4 (k16 MMA steps)
#define NTILE  (N_TOK / TPB)     // 128 token tiles
#define NSLICE 8                 // K-slices (512 k each)
#define NUNIT  (NTILE * NSLICE)  // 1024
#define NCTA   148               // persistent CTAs
#define PAD    72                // x row stride in floats

typedef unsigned int u32;

// Packed W fp16 fragment quads: [kchunk][ks][n][t] -> {b0_hi, b1_hi, b0_lo*2048, b1_lo*2048}
__device__ __align__(16) uint4 g_Wq[(DIM / KC) * KSTEPS * NEXP * 4];  // 65536 quads, 1 MB
__device__ __align__(16) float g_part[NUNIT * TPB * NEXP];            // 33.5 MB partials
__device__ float g_partial[NTILE * NEXP];

// ---- smem byte offsets (stage 1) ----
#define XS(b)  ((b) * 36864)                    // 128 x 72 floats
#define WQ(b)  (73728 + (b) * 16384)            // 1024 uint4
#define SMEM_BYTES 106496

// split (x0, x1) -> hi fp16x2 (low half = x0), lo fp16x2 = ((x - hi) * 2048)
static __device__ __forceinline__ void split2(float x0, float x1, u32& h, u32& l) {
    asm("{\n\t"
        ".reg .b16 h0, h1;\n\t"
        ".reg .f32 u0, u1, r0, r1;\n\t"
        "cvt.rn.f16.f32 h0, %2;\n\t"
        "cvt.rn.f16.f32 h1, %3;\n\t"
        "mov.b32 %0, {h0, h1};\n\t"
        "cvt.f32.f16 u0, h0;\n\t"
        "cvt.f32.f16 u1, h1;\n\t"
        "sub.f32 r0, %2, u0;\n\t"
        "sub.f32 r1, %3, u1;\n\t"
        "mul.f32 r0, r0, 0f45000000;\n\t"
        "mul.f32 r1, r1, 0f45000000;\n\t"
        "cvt.rn.f16x2.f32 %1, r1, r0;\n\t"
        "}" : "=r"(h), "=r"(l) : "f"(x0), "f"(x1));
}

static __device__ __forceinline__ void mma_f16(float* c, u32 a0, u32 a1, u32 a2,
                                               u32 a3, u32 b0, u32 b1) {
    asm volatile(
        "mma.sync.aligned.m16n8k16.row.col.f32.f16.f16.f32 "
        "{%0,%1,%2,%3}, {%4,%5,%6,%7}, {%8,%9}, {%0,%1,%2,%3};"
        : "+f"(c[0]), "+f"(c[1]), "+f"(c[2]), "+f"(c[3])
        : "r"(a0), "r"(a1), "r"(a2), "r"(a3), "r"(b0), "r"(b1));
}
static __device__ __forceinline__ void mma_f16_z(float* d, u32 a0, u32 a1, u32 a2,
                                                 u32 a3, u32 b0, u32 b1) {
    asm volatile(
        "mma.sync.aligned.m16n8k16.row.col.f32.f16.f16.f32 "
        "{%0,%1,%2,%3}, {%4,%5,%6,%7}, {%8,%9}, {%10,%10,%10,%10};"
        : "=f"(d[0]), "=f"(d[1]), "=f"(d[2]), "=f"(d[3])
        : "r"(a0), "r"(a1), "r"(a2), "r"(a3), "r"(b0), "r"(b1), "f"(0.0f));
}

// ---- W pre-pack: fp32 -> fp16 split fragment quads ----
extern "C" __global__ void wconv_kernel(const float* __restrict__ W) {
    const int idx = blockIdx.x * blockDim.x + threadIdx.x;   // 65536 quads
    const int t  = idx & 3;
    const int n  = (idx >> 2) & 63;
    const int ks = (idx >> 8) & 3;
    const int c  = idx >> 10;
    const int k0 = c * KC + ks * 16;
    const float* wr = W + (size_t)n * DIM + k0;
    uint4 q;
    split2(wr[2 * t],     wr[2 * t + 1], q.x, q.z);
    split2(wr[2 * t + 8], wr[2 * t + 9], q.y, q.w);
    g_Wq[idx] = q;
}

// ---- stage 1: persistent GEMM over (unit, chunk); writes fp32 partials ----
extern "C" __global__ void __launch_bounds__(NTHR, 1)
moe_stage1(const float* __restrict__ x) {
    extern __shared__ char sm[];
    const int bid  = blockIdx.x;                 // 0..147
    const int tid  = threadIdx.x;
    const int wid  = tid >> 5;
    const int lane = tid & 31;
    const int g    = lane >> 2;
    const int t    = lane & 3;
    const int warpM = wid * 16;

    // 1024 = 148*6 + 136: bids 0..135 get 7 units, 136..147 get 6
    const int nu   = (bid < NUNIT - NCTA * 6) ? 7 : 6;
    const int totc = nu * 8;                     // chunks total for this CTA

    // issue cp.async for global chunk index gc
    auto issue_chunk = [&](int gc) {
        const int u     = bid + NCTA * (gc >> 3);
        const int tok0  = (u & (NTILE - 1)) * TPB;
        const int ck    = (u >> 7) * 8 + (gc & 7);    // global k-chunk 0..63
        const int kc    = ck * KC;
        const int b     = gc & 1;
#pragma unroll
        for (int i = 0; i < 8; i++) {
            const int flat = tid + (i << 8);
            const int row = flat >> 4;
            const int j   = flat & 15;
            __pipeline_memcpy_async(sm + XS(b) + row * (PAD * 4) + j * 16,
                                    x + (size_t)(tok0 + row) * DIM + kc + 4 * j, 16);
        }
        const uint4* src = g_Wq + (size_t)ck * (KSTEPS * NEXP * 4);
#pragma unroll
        for (int i = 0; i < 4; i++) {
            const int flat = tid + (i << 8);
            __pipeline_memcpy_async(sm + WQ(b) + flat * 16, src + flat, 16);
        }
    };

    float accM[8][4];    // master fp32 (per unit)
    float hh[8][4];      // per-chunk hi*hi (reset via mma_f16_z)
    float accx[8][4];    // cross terms fp32, carries x2048 scale (per unit)
#pragma unroll
    for (int j = 0; j < 8; j++)
#pragma unroll
        for (int q = 0; q < 4; q++) { accM[j][q] = 0.f; accx[j][q] = 0.f; }

    issue_chunk(0);
    __pipeline_commit();

#pragma unroll 1
    for (int gc = 0; gc < totc; gc++) {
        const int b = gc & 1;
        if (gc + 1 < totc) issue_chunk(gc + 1);
        __pipeline_commit();
        __pipeline_wait_prior((gc + 1 < totc) ? 1 : 0);
        __syncthreads();

        const float* xs = reinterpret_cast<const float*>(sm + XS(b));
        const uint4* wq = reinterpret_cast<const uint4*>(sm + WQ(b));

#pragma unroll
        for (int ks = 0; ks < KSTEPS; ks++) {
            const int k0 = ks * 16;
            const int r0 = warpM + g;
            const float2 v0 = *reinterpret_cast<const float2*>(xs + r0 * PAD + k0 + 2 * t);
            const float2 v1 = *reinterpret_cast<const float2*>(xs + (r0 + 8) * PAD + k0 + 2 * t);
            const float2 v2 = *reinterpret_cast<const float2*>(xs + r0 * PAD + k0 + 2 * t + 8);
            const float2 v3 = *reinterpret_cast<const float2*>(xs + (r0 + 8) * PAD + k0 + 2 * t + 8);
            u32 ah0, ah1, ah2, ah3, al0, al1, al2, al3;
            split2(v0.x, v0.y, ah0, al0);
            split2(v1.x, v1.y, ah1, al1);
            split2(v2.x, v2.y, ah2, al2);
            split2(v3.x, v3.y, ah3, al3);

            const uint4* wrow = wq + (ks * NEXP + g) * 4 + t;
#pragma unroll
            for (int j = 0; j < 8; j++) {
                const uint4 q = wrow[j * 32];
                if (ks == 0) mma_f16_z(hh[j], ah0, ah1, ah2, ah3, q.x, q.y);
                else         mma_f16(hh[j], ah0, ah1, ah2, ah3, q.x, q.y);
                mma_f16(accx[j], ah0, ah1, ah2, ah3, q.z, q.w);
                mma_f16(accx[j], al0, al1, al2, al3, q.x, q.y);
            }
        }
#pragma unroll
        for (int j = 0; j < 8; j++)
#pragma unroll
            for (int q = 0; q < 4; q++) accM[j][q] += hh[j][q];
        __syncthreads();

        // unit boundary: flush partial (registers -> global), reset accumulators
        if ((gc & 7) == 7) {
            const int u = bid + NCTA * (gc >> 3);
            float* dst = g_part + (size_t)u * (TPB * NEXP);
            const int r0 = warpM + g;
            const float s = 4.8828125e-4f;   // 1/2048
#pragma unroll
            for (int j = 0; j < 8; j++) {
                const int col = 8 * j + 2 * t;
                const float f0 = fmaf(accx[j][0], s, accM[j][0]);
                const float f1 = fmaf(accx[j][1], s, accM[j][1]);
                const float f2 = fmaf(accx[j][2], s, accM[j][2]);
                const float f3 = fmaf(accx[j][3], s, accM[j][3]);
                *reinterpret_cast<float2*>(dst + r0 * NEXP + col)       = make_float2(f0, f1);
                *reinterpret_cast<float2*>(dst + (r0 + 8) * NEXP + col) = make_float2(f2, f3);
                accM[j][0] = 0.f; accM[j][1] = 0.f; accM[j][2] = 0.f; accM[j][3] = 0.f;
                accx[j][0] = 0.f; accx[j][1] = 0.f; accx[j][2] = 0.f; accx[j][3] = 0.f;
            }
        }
    }
}

// ---- stage 2: reduce 8 K-slice partials, softmax, top-8, outputs ----
extern "C" __global__ void __launch_bounds__(TPB, 1)
moe_reduce(const float* __restrict__ bias, float* __restrict__ out) {
    __shared__ float ps[TPB * 66];
    __shared__ float bs[NEXP];
    const int tile = blockIdx.x;
    const int tok  = threadIdx.x;

    float lv[NEXP];
    {
        const float4* p0 = reinterpret_cast<const float4*>(
            g_part + ((size_t)tile * TPB + tok) * NEXP);
        float4 a[16];
#pragma unroll
        for (int j = 0; j < 16; j++) a[j] = p0[j];
#pragma unroll
        for (int s = 1; s < NSLICE; s++) {
            const float4* p = reinterpret_cast<const float4*>(
                g_part + (((size_t)s * NTILE + tile) * TPB + tok) * NEXP);
#pragma unroll
            for (int j = 0; j < 16; j++) {
                const float4 v = p[j];
                a[j].x += v.x; a[j].y += v.y; a[j].z += v.z; a[j].w += v.w;
            }
        }
#pragma unroll
        for (int j = 0; j < 16; j++) {
            lv[4 * j + 0] = a[j].x; lv[4 * j + 1] = a[j].y;
            lv[4 * j + 2] = a[j].z; lv[4 * j + 3] = a[j].w;
        }
    }
    if (tok < NEXP) bs[tok] = bias[tok];
    __syncthreads();

    float mx = -INFINITY;
#pragma unroll
    for (int e = 0; e < NEXP; e++) {
        lv[e] += bs[e];
        mx = fmaxf(mx, lv[e]);
    }
    float ssum = 0.0f;
#pragma unroll
    for (int e = 0; e < NEXP; e++) {
        lv[e] = expf(lv[e] - mx);
        ssum += lv[e];
    }
    const float inv = 1.0f / ssum;
#pragma unroll
    for (int e = 0; e < NEXP; e++) {
        lv[e] *= inv;
        ps[tok * 66 + e] = lv[e];
    }
    __syncthreads();

    if (tok < NEXP) {
        float cs = 0.0f;
        for (int tt = 0; tt < TPB; tt++) cs += ps[tt * 66 + tok];
        g_partial[tile * NEXP + tok] = cs;
    }

    const int gt = tile * TPB + tok;
    float prevV = INFINITY;
    int   prevE = -1;
    float* o_ids = out;
    float* o_p   = out + (size_t)N_TOK * 8;
#pragma unroll
    for (int r = 0; r < TOPK; r++) {
        float bv = -INFINITY;
        int   be = 0;
#pragma unroll
        for (int e = 0; e < NEXP; e++) {
            const float v = lv[e];
            const bool elig = (v < prevV) || (v == prevV && e > prevE);
            if (elig && v > bv) { bv = v; be = e; }
        }
        o_ids[(size_t)gt * 8 + r] = (float)be;
        o_p[(size_t)gt * 8 + r]   = bv;
        prevV = bv; prevE = be;
    }
    out[(size_t)N_TOK * 16 + gt * 2 + 0] = 0.0f;
    out[(size_t)N_TOK * 16 + gt * 2 + 1] = 1.0f;
    out[(size_t)N_TOK * 18 + gt * 2 + 0] = 0.5f;
    out[(size_t)N_TOK * 18 + gt * 2 + 1] = 0.5f;
}

// 512 threads: 8 tile-groups x 64 experts, then tree-reduce
__global__ void aux_kernel(float* __restrict__ out) {
    __shared__ float part[8][NEXP];
    __shared__ float sq[NEXP];
    const int e  = threadIdx.x & 63;
    const int gr = threadIdx.x >> 6;
    float s = 0.0f;
#pragma unroll
    for (int b = gr; b < NTILE; b += 8) s += g_partial[b * NEXP + e];
    part[gr][e] = s;
    __syncthreads();
    if (threadIdx.x < NEXP) {
        float tot = 0.0f;
#pragma unroll
        for (int i = 0; i < 8; i++) tot += part[i][threadIdx.x];
        const float m = tot / (float)N_TOK;
        sq[threadIdx.x] = m * m;
    }
    __syncthreads();
    if (threadIdx.x == 0) {
        float tot = 0.0f;
        for (int i = 0; i < NEXP; i++) tot += sq[i];
        out[(size_t)N_TOK * 20] = 0.01f * (tot / (float)NEXP);
    }
}

extern "C" void kernel_launch(void* const* d_in, const int* in_sizes, int n_in,
                              void* d_out, int out_size) {
    const float* x    = (const float*)d_in[0];
    const float* W    = (const float*)d_in[1];
    const float* bias = (const float*)d_in[2];
    float* out = (float*)d_out;

    cudaFuncSetAttribute(moe_stage1, cudaFuncAttributeMaxDynamicSharedMemorySize,
                         SMEM_BYTES);
    wconv_kernel<<<256, 256>>>(W);
    moe_stage1<<<NCTA, NTHR, SMEM_BYTES>>>(x);
    moe_reduce<<<NTILE, TPB>>>(bias, out);
    aux_kernel<<<1, 512>>>(out);
}